// round 5
// baseline (speedup 1.0000x reference)
#include <cuda_runtime.h>
#include <cuda_bf16.h>

// RITS recurrence v4: 128 CTAs x 256 threads, 2 samples/CTA, T=512 on-chip.
//  - 3 barriers/step (was 6): all k-split reductions + pointwise epilogues
//    happen in-warp via shfl_xor; zero partial-sum smem traffic.
//  - Phase C: thread owns TWO fused [W_lstm;U_lstm] columns (i,g)/(f,o)
//    paired in a lane-quad, half-k each -> activation broadcasts halved,
//    LSTM gates computed via quad shuffles (no zbuf, no C2 phase).
//  - Fused concat activations: actB=[xc|gx|m], actC=[cc|m|hdec].

#define TT 512
#define NIMP (256L * 3 * 512 * 64)
typedef unsigned long long ull;

#define FMA2(acc, a, b) \
    asm("fma.rn.f32x2 %0, %1, %2, %0;" : "+l"(acc) : "l"(a), "l"(b))

__device__ __forceinline__ ull pk2(float x, float y) {
    ull r; asm("mov.b64 %0, {%1, %2};" : "=l"(r) : "f"(x), "f"(y)); return r;
}
__device__ __forceinline__ float2 upk(ull v) {
    float2 r; asm("mov.b64 {%0, %1}, %2;" : "=f"(r.x), "=f"(r.y) : "l"(v)); return r;
}
__device__ __forceinline__ float sigf(float x) { return 1.f / (1.f + __expf(-x)); }

__global__ __launch_bounds__(256, 1) void rits_kernel(
    const float* __restrict__ inputs,
    const float* __restrict__ W_hist, const float* __restrict__ b_hist,
    const float* __restrict__ W_feat, const float* __restrict__ b_feat,
    const float* __restrict__ W_gx,   const float* __restrict__ b_gx,
    const float* __restrict__ W_gh,   const float* __restrict__ b_gh,
    const float* __restrict__ W_beta, const float* __restrict__ b_beta,
    const float* __restrict__ W_lstm, const float* __restrict__ U_lstm,
    const float* __restrict__ b_lstm,
    const float* __restrict__ W_out,  const float* __restrict__ b_out,
    float* __restrict__ out)
{
    extern __shared__ __align__(16) float sm[];
    float* sWh2  = sm;             // 4096  W_hist pairs {w[2q][j],w[2q+1][j]}
    float* sWgh2 = sWh2  + 4096;   // 4096  W_gh pairs
    float* sWzb  = sWgh2 + 4096;   // 12288 fused [W_feat_c(q<32) ; W_beta] pairs
    float* sWgx  = sWzb  + 12288;  // 64    diag(W_gx)
    float* sbh   = sWgx + 64;
    float* sbf   = sbh  + 64;
    float* sbgx  = sbf  + 64;
    float* sbb   = sbgx + 64;
    float* sbgh  = sbb  + 64;
    float* sbl   = sbgh + 64;      // 256
    float* hS    = sbl  + 256;     // 128  h [s*64+j]
    float* cS    = hS   + 128;     // 128
    float* xhat  = cS   + 128;     // 128
    float* actB  = xhat + 128;     // 384  [s][xc(64)|gx(64)|m(64)]
    float* actC  = actB + 384;     // 384  [s][cc(64)|m(64)|hdec(64)]
    float* inb   = actC + 384;     // 2*384 double-buffered [c*128 + s*64 + k]

    const int tid  = threadIdx.x;
    const int bid  = blockIdx.x;
    const int lane = tid & 31;
    const int w    = tid >> 5;

    // ---- pack smem weights ----
    for (int i = tid; i < 2048; i += 256) {
        int q = i >> 6, j = i & 63;
        *(float2*)&sWh2[i * 2]  = make_float2(W_hist[(2*q)*64 + j], W_hist[(2*q+1)*64 + j]);
        *(float2*)&sWgh2[i * 2] = make_float2(W_gh[(2*q)*64 + j],   W_gh[(2*q+1)*64 + j]);
    }
    for (int i = tid; i < 6144; i += 256) {
        int q = i >> 6, j = i & 63;
        float a, b;
        if (q < 32) {
            int k0 = 2 * q;
            a = (k0     == j) ? 0.f : W_feat[k0 * 64 + j];
            b = (k0 + 1 == j) ? 0.f : W_feat[(k0 + 1) * 64 + j];
        } else {
            int k0 = 2 * (q - 32);
            a = W_beta[k0 * 64 + j];
            b = W_beta[(k0 + 1) * 64 + j];
        }
        *(float2*)&sWzb[i * 2] = make_float2(a, b);
    }
    if (tid < 64) {
        sWgx[tid] = W_gx[tid * 64 + tid];
        sbh[tid]  = b_hist[tid];
        sbf[tid]  = b_feat[tid];
        sbgx[tid] = b_gx[tid];
        sbb[tid]  = b_beta[tid];
        sbgh[tid] = b_gh[tid];
    }
    sbl[tid] = b_lstm[tid];
    if (tid < 128) { hS[tid] = 0.f; cS[tid] = 0.f; }

    // ---- phase C register weights: 2 fused columns, half k ----
    // lane: khC = lane&1 (k-half), ci = w*16 + (lane>>1); jC = ci>>1; gsC = ci&1
    // colA = gsC*64 + jC  (gate i or f),  colB = colA + 128  (gate g or o)
    const int khC = lane & 1;
    const int ciC = w * 16 + (lane >> 1);
    const int jC  = ciC >> 1;
    const int gsC = ciC & 1;
    const int colA = gsC * 64 + jC;
    const int colB = colA + 128;
    ull wA[48], wB[48];
#pragma unroll
    for (int q = 0; q < 48; q++) {
        int r0 = 2 * (khC * 48 + q), r1 = r0 + 1;
        float a0 = (r0 < 128) ? W_lstm[r0 * 256 + colA] : U_lstm[(r0 - 128) * 256 + colA];
        float a1 = (r1 < 128) ? W_lstm[r1 * 256 + colA] : U_lstm[(r1 - 128) * 256 + colA];
        float b0 = (r0 < 128) ? W_lstm[r0 * 256 + colB] : U_lstm[(r0 - 128) * 256 + colB];
        float b1 = (r1 < 128) ? W_lstm[r1 * 256 + colB] : U_lstm[(r1 - 128) * 256 + colB];
        wA[q] = pk2(a0, a1);
        wB[q] = pk2(b0, b1);
    }

    // ---- input loader mapping (threads 0..191) ----
    const int ls = tid / 96;
    const int lr = tid % 96;
    const int lc = lr / 32;             // 0=x 1=m 2=d
    const int ll = lr % 32;
    const long lbase = ((long)(2 * bid + ls) * 3 + lc) * TT * 64;

    if (tid < 192) {
        float2 v = *(const float2*)&inputs[lbase + 2 * ll];
        *(float2*)&inb[lc * 128 + ls * 64 + 2 * ll] = v;
    }

    // ---- phase A / B lane decompositions ----
    const int jobA = w * 16 + (lane & 15);   // [0,128): g*64 + j
    const int khA  = lane >> 4;
    const int gA   = jobA >> 6;              // warp-uniform (w<4: 0, w>=4: 1)
    const int jA   = jobA & 63;
    const int qqB  = lane & 3;               // k-quarter
    const int jjB  = w * 8 + (lane >> 2);    // [0,64)

    __syncthreads();

    int p = 0;
    for (int t = 0; t < TT; t++) {
        float* bufc = inb + p * 384;

        float2 pf = make_float2(0.f, 0.f);
        if (tid < 192 && t + 1 < TT)
            pf = *(const float2*)&inputs[lbase + (long)(t + 1) * 64 + 2 * ll];

        // ===== Phase A: x_hat pre (h@W_hist) | gamma_h pre (d@W_gh) =====
        {
            const float* act = gA ? (bufc + 256) : hS;
            const float* W   = gA ? sWgh2 : sWh2;
            ull a0 = 0, a1 = 0;
#pragma unroll
            for (int i = 0; i < 8; i++) {
                int k = khA * 32 + 4 * i, q = k >> 1;
                ulonglong2 x0 = *(const ulonglong2*)&act[k];
                ulonglong2 x1 = *(const ulonglong2*)&act[64 + k];
                ull wa = *(const ull*)&W[(q * 64 + jA) * 2];
                ull wb = *(const ull*)&W[((q + 1) * 64 + jA) * 2];
                FMA2(a0, wa, x0.x); FMA2(a0, wb, x0.y);
                FMA2(a1, wa, x1.x); FMA2(a1, wb, x1.y);
            }
            float2 r0 = upk(a0), r1 = upk(a1);
            float v0 = r0.x + r0.y, v1 = r1.x + r1.y;
            v0 += __shfl_xor_sync(0xffffffffu, v0, 16);
            v1 += __shfl_xor_sync(0xffffffffu, v1, 16);
            if (lane < 16) {
                if (gA == 0) {
                    float xh0 = v0 + sbh[jA], xh1 = v1 + sbh[jA];
                    xhat[jA]      = xh0;
                    xhat[64 + jA] = xh1;
                    float x0s = bufc[jA],       m0 = bufc[128 + jA],      d0 = bufc[256 + jA];
                    float x1s = bufc[64 + jA],  m1 = bufc[192 + jA],      d1 = bufc[320 + jA];
                    actB[jA]            = m0 * x0s + (1.f - m0) * xh0;
                    actB[192 + jA]      = m1 * x1s + (1.f - m1) * xh1;
                    actB[64 + jA]       = __expf(-fmaxf(d0 * sWgx[jA] + sbgx[jA], 0.f));
                    actB[192 + 64 + jA] = __expf(-fmaxf(d1 * sWgx[jA] + sbgx[jA], 0.f));
                    actB[128 + jA]      = m0;
                    actB[192 + 128 + jA] = m1;
                    long n0 = 2 * bid, n1 = n0 + 1;
                    out[((n0 * 3 + 0) * (long)TT + t) * 64 + jA] = xh0;
                    out[((n1 * 3 + 0) * (long)TT + t) * 64 + jA] = xh1;
                } else {
                    float gh0 = __expf(-fmaxf(v0 + sbgh[jA], 0.f));
                    float gh1 = __expf(-fmaxf(v1 + sbgh[jA], 0.f));
                    actC[128 + jA]       = hS[jA]      * gh0;
                    actC[192 + 128 + jA] = hS[64 + jA] * gh1;
                }
            }
        }
        __syncthreads();

        // ===== Phase B: z_hat (xc@W_feat_c) + beta pre ([gx;m]@W_beta) =====
        // fused weight sWzb: act float index == 2q for all 96 pairs.
        {
            ull z0 = 0, z1 = 0, b0 = 0, b1 = 0;
#pragma unroll
            for (int i = 0; i < 4; i++) {            // z_hat: pairs qq*8..qq*8+7
                int q = qqB * 8 + 2 * i;
                ulonglong2 x0 = *(const ulonglong2*)&actB[2 * q];
                ulonglong2 x1 = *(const ulonglong2*)&actB[192 + 2 * q];
                ull wa = *(const ull*)&sWzb[(q * 64 + jjB) * 2];
                ull wb = *(const ull*)&sWzb[((q + 1) * 64 + jjB) * 2];
                FMA2(z0, wa, x0.x); FMA2(z0, wb, x0.y);
                FMA2(z1, wa, x1.x); FMA2(z1, wb, x1.y);
            }
#pragma unroll
            for (int i = 0; i < 8; i++) {            // beta: pairs 32+qq*16..+15
                int q = 32 + qqB * 16 + 2 * i;
                ulonglong2 x0 = *(const ulonglong2*)&actB[2 * q];
                ulonglong2 x1 = *(const ulonglong2*)&actB[192 + 2 * q];
                ull wa = *(const ull*)&sWzb[(q * 64 + jjB) * 2];
                ull wb = *(const ull*)&sWzb[((q + 1) * 64 + jjB) * 2];
                FMA2(b0, wa, x0.x); FMA2(b0, wb, x0.y);
                FMA2(b1, wa, x1.x); FMA2(b1, wb, x1.y);
            }
            float2 rz0 = upk(z0), rz1 = upk(z1), rb0 = upk(b0), rb1 = upk(b1);
            float zv0 = rz0.x + rz0.y, zv1 = rz1.x + rz1.y;
            float bv0 = rb0.x + rb0.y, bv1 = rb1.x + rb1.y;
#pragma unroll
            for (int off = 1; off <= 2; off <<= 1) {
                zv0 += __shfl_xor_sync(0xffffffffu, zv0, off);
                zv1 += __shfl_xor_sync(0xffffffffu, zv1, off);
                bv0 += __shfl_xor_sync(0xffffffffu, bv0, off);
                bv1 += __shfl_xor_sync(0xffffffffu, bv1, off);
            }
            if ((lane & 3) == 0) {
                float zh0 = zv0 + sbf[jjB], zh1 = zv1 + sbf[jjB];
                float be0 = sigf(bv0 + sbb[jjB]);
                float be1 = sigf(bv1 + sbb[jjB]);
                float ch0 = be0 * zh0 + (1.f - be0) * xhat[jjB];
                float ch1 = be1 * zh1 + (1.f - be1) * xhat[64 + jjB];
                float x0s = bufc[jjB],      m0 = bufc[128 + jjB];
                float x1s = bufc[64 + jjB], m1 = bufc[192 + jjB];
                actC[jjB]            = m0 * x0s + (1.f - m0) * ch0;
                actC[192 + jjB]      = m1 * x1s + (1.f - m1) * ch1;
                actC[64 + jjB]       = m0;
                actC[192 + 64 + jjB] = m1;
                long n0 = 2 * bid, n1 = n0 + 1;
                out[((n0 * 3 + 1) * (long)TT + t) * 64 + jjB] = zh0;
                out[((n1 * 3 + 1) * (long)TT + t) * 64 + jjB] = zh1;
                out[((n0 * 3 + 2) * (long)TT + t) * 64 + jjB] = ch0;
                out[((n1 * 3 + 2) * (long)TT + t) * 64 + jjB] = ch1;
            }
        }
        __syncthreads();

        // ===== Phase C: z = [cc;m;hdec] @ [W_lstm;U], 2 cols/thread, half k ==
        {
            ull aA0 = 0, aA1 = 0, aB0 = 0, aB1 = 0;
#pragma unroll
            for (int i = 0; i < 24; i++) {
                int k4 = khC * 96 + 4 * i;
                ulonglong2 x0 = *(const ulonglong2*)&actC[k4];
                ulonglong2 x1 = *(const ulonglong2*)&actC[192 + k4];
                FMA2(aA0, wA[2*i],   x0.x); FMA2(aA0, wA[2*i+1], x0.y);
                FMA2(aA1, wA[2*i],   x1.x); FMA2(aA1, wA[2*i+1], x1.y);
                FMA2(aB0, wB[2*i],   x0.x); FMA2(aB0, wB[2*i+1], x0.y);
                FMA2(aB1, wB[2*i],   x1.x); FMA2(aB1, wB[2*i+1], x1.y);
            }
            float2 r;
            r = upk(aA0); float vA0 = r.x + r.y;
            r = upk(aA1); float vA1 = r.x + r.y;
            r = upk(aB0); float vB0 = r.x + r.y;
            r = upk(aB1); float vB1 = r.x + r.y;
            // reduce k-halves (partner lane^1)
            vA0 += __shfl_xor_sync(0xffffffffu, vA0, 1);
            vA1 += __shfl_xor_sync(0xffffffffu, vA1, 1);
            vB0 += __shfl_xor_sync(0xffffffffu, vB0, 1);
            vB1 += __shfl_xor_sync(0xffffffffu, vB1, 1);
            // exchange with gate partner (lane^2): (i,g) <-> (f,o)
            float pA0 = __shfl_xor_sync(0xffffffffu, vA0, 2);
            float pA1 = __shfl_xor_sync(0xffffffffu, vA1, 2);
            float pB0 = __shfl_xor_sync(0xffffffffu, vB0, 2);
            float pB1 = __shfl_xor_sync(0xffffffffu, vB1, 2);
            if ((lane & 3) == 0) {
                // own: i (vA), g (vB); partner: f (pA), o (pB)
                float zi0 = vA0 + sbl[jC],        zi1 = vA1 + sbl[jC];
                float zf0 = pA0 + sbl[64 + jC],   zf1 = pA1 + sbl[64 + jC];
                float zg0 = vB0 + sbl[128 + jC],  zg1 = vB1 + sbl[128 + jC];
                float zo0 = pB0 + sbl[192 + jC],  zo1 = pB1 + sbl[192 + jC];
                float cn0 = sigf(zf0) * cS[jC]      + sigf(zi0) * tanhf(zg0);
                float cn1 = sigf(zf1) * cS[64 + jC] + sigf(zi1) * tanhf(zg1);
                cS[jC]      = cn0;
                cS[64 + jC] = cn1;
                hS[jC]      = sigf(zo0) * tanhf(cn0);
                hS[64 + jC] = sigf(zo1) * tanhf(cn1);
            }
        }
        if (tid < 192 && t + 1 < TT)
            *(float2*)&inb[(p ^ 1) * 384 + lc * 128 + ls * 64 + 2 * ll] = pf;
        p ^= 1;
        __syncthreads();
    }

    // ===== predictions: sigmoid(h_last @ W_out + b_out) =====
    if (tid < 64) {
        int s = tid >> 5, l = tid & 31;
        float v = hS[s * 64 + l] * W_out[l] + hS[s * 64 + 32 + l] * W_out[32 + l];
#pragma unroll
        for (int off = 16; off; off >>= 1)
            v += __shfl_down_sync(0xffffffffu, v, off);
        if (l == 0)
            out[NIMP + 2 * bid + s] = 1.f / (1.f + __expf(-(v + b_out[0])));
    }
}

extern "C" void kernel_launch(void* const* d_in, const int* in_sizes, int n_in,
                              void* d_out, int out_size)
{
    const float* inputs = (const float*)d_in[0];
    const float* W_hist = (const float*)d_in[1];
    const float* b_hist = (const float*)d_in[2];
    const float* W_feat = (const float*)d_in[3];
    const float* b_feat = (const float*)d_in[4];
    const float* W_gx   = (const float*)d_in[5];
    const float* b_gx   = (const float*)d_in[6];
    const float* W_gh   = (const float*)d_in[7];
    const float* b_gh   = (const float*)d_in[8];
    const float* W_beta = (const float*)d_in[9];
    const float* b_beta = (const float*)d_in[10];
    const float* W_lstm = (const float*)d_in[11];
    const float* U_lstm = (const float*)d_in[12];
    const float* b_lstm = (const float*)d_in[13];
    const float* W_out  = (const float*)d_in[14];
    const float* b_out  = (const float*)d_in[15];

    const int smem_bytes = 23040 * (int)sizeof(float);   // 92,160 B
    cudaFuncSetAttribute(rits_kernel,
                         cudaFuncAttributeMaxDynamicSharedMemorySize, smem_bytes);

    rits_kernel<<<128, 256, smem_bytes>>>(
        inputs, W_hist, b_hist, W_feat, b_feat, W_gx, b_gx, W_gh, b_gh,
        W_beta, b_beta, W_lstm, U_lstm, b_lstm, W_out, b_out,
        (float*)d_out);
}

// round 6
// speedup vs baseline: 1.0081x; 1.0081x over previous
#include <cuda_runtime.h>
#include <cuda_bf16.h>

// RITS recurrence v5: v2 skeleton + in-warp reductions, 3 barriers/step.
//  - 128 CTAs x 256 thr, 2 samples/CTA, T=512 on-chip.
//  - Phase A/B: k-split across lanes, shfl_xor reduce, fused epilogues.
//  - Phase C: one fused [W_lstm;U_lstm] column per thread (full k=192,
//    96 ull regs, broadcast LDS.128 like v2) with gates of the same j
//    mapped to a lane-quad; LSTM cell computed via 3 shfl_xor (no zbuf).

#define TT 512
#define NIMP (256L * 3 * 512 * 64)
typedef unsigned long long ull;

#define FMA2(acc, a, b) \
    asm("fma.rn.f32x2 %0, %1, %2, %0;" : "+l"(acc) : "l"(a), "l"(b))

__device__ __forceinline__ ull pk2(float x, float y) {
    ull r; asm("mov.b64 %0, {%1, %2};" : "=l"(r) : "f"(x), "f"(y)); return r;
}
__device__ __forceinline__ float2 upk(ull v) {
    float2 r; asm("mov.b64 {%0, %1}, %2;" : "=f"(r.x), "=f"(r.y) : "l"(v)); return r;
}
__device__ __forceinline__ float sigf(float x) { return 1.f / (1.f + __expf(-x)); }

__global__ __launch_bounds__(256, 1) void rits_kernel(
    const float* __restrict__ inputs,
    const float* __restrict__ W_hist, const float* __restrict__ b_hist,
    const float* __restrict__ W_feat, const float* __restrict__ b_feat,
    const float* __restrict__ W_gx,   const float* __restrict__ b_gx,
    const float* __restrict__ W_gh,   const float* __restrict__ b_gh,
    const float* __restrict__ W_beta, const float* __restrict__ b_beta,
    const float* __restrict__ W_lstm, const float* __restrict__ U_lstm,
    const float* __restrict__ b_lstm,
    const float* __restrict__ W_out,  const float* __restrict__ b_out,
    float* __restrict__ out)
{
    extern __shared__ __align__(16) float sm[];
    float* sWh2  = sm;             // 4096  W_hist pairs {w[2q][j],w[2q+1][j]}
    float* sWgh2 = sWh2  + 4096;   // 4096  W_gh pairs
    float* sWzb  = sWgh2 + 4096;   // 12288 fused [W_feat_c(q<32) ; W_beta] pairs
    float* sWgx  = sWzb  + 12288;  // 64    diag(W_gx)
    float* sbh   = sWgx + 64;
    float* sbf   = sbh  + 64;
    float* sbgx  = sbf  + 64;
    float* sbb   = sbgx + 64;
    float* sbgh  = sbb  + 64;
    float* sbl   = sbgh + 64;      // 256
    float* hS    = sbl  + 256;     // 128  h [s*64+j]
    float* cS    = hS   + 128;     // 128
    float* xhat  = cS   + 128;     // 128  [s*64+j]
    float* actB  = xhat + 128;     // 384  [s][xc(64)|gx(64)|m(64)]
    float* actC  = actB + 384;     // 384  [s][cc(64)|m(64)|hdec(64)]
    float* inb   = actC + 384;     // 2*384 double-buffered [c*128 + s*64 + k]

    const int tid  = threadIdx.x;
    const int bid  = blockIdx.x;
    const int lane = tid & 31;
    const int w    = tid >> 5;

    // ---- pack smem weights ----
    for (int i = tid; i < 2048; i += 256) {
        int q = i >> 6, j = i & 63;
        *(float2*)&sWh2[i * 2]  = make_float2(W_hist[(2*q)*64 + j], W_hist[(2*q+1)*64 + j]);
        *(float2*)&sWgh2[i * 2] = make_float2(W_gh[(2*q)*64 + j],   W_gh[(2*q+1)*64 + j]);
    }
    for (int i = tid; i < 6144; i += 256) {
        int q = i >> 6, j = i & 63;
        float a, b;
        if (q < 32) {
            int k0 = 2 * q;
            a = (k0     == j) ? 0.f : W_feat[k0 * 64 + j];
            b = (k0 + 1 == j) ? 0.f : W_feat[(k0 + 1) * 64 + j];
        } else {
            int k0 = 2 * (q - 32);
            a = W_beta[k0 * 64 + j];
            b = W_beta[(k0 + 1) * 64 + j];
        }
        *(float2*)&sWzb[i * 2] = make_float2(a, b);
    }
    if (tid < 64) {
        sWgx[tid] = W_gx[tid * 64 + tid];
        sbh[tid]  = b_hist[tid];
        sbf[tid]  = b_feat[tid];
        sbgx[tid] = b_gx[tid];
        sbb[tid]  = b_beta[tid];
        sbgh[tid] = b_gh[tid];
    }
    sbl[tid] = b_lstm[tid];
    if (tid < 128) { hS[tid] = 0.f; cS[tid] = 0.f; }

    // ---- phase C register weights: one fused column, gates in lane-quads --
    // lane = jl*4 + gate ; column = gate*64 + (w*8 + jl)
    const int gC  = lane & 3;
    const int jC  = w * 8 + (lane >> 2);
    const int colC = gC * 64 + jC;
    ull wc[96];                     // rows: [c_c(64) | m(64) | hdec(64)] pairs
#pragma unroll
    for (int q = 0; q < 96; q++) {
        int r0 = 2 * q, r1 = r0 + 1;
        float a0 = (r0 < 128) ? W_lstm[r0 * 256 + colC] : U_lstm[(r0 - 128) * 256 + colC];
        float a1 = (r1 < 128) ? W_lstm[r1 * 256 + colC] : U_lstm[(r1 - 128) * 256 + colC];
        wc[q] = pk2(a0, a1);
    }
    const float blC = b_lstm[colC];

    // ---- input loader mapping (threads 0..191) ----
    const int ls = tid / 96;
    const int lr = tid % 96;
    const int lc = lr / 32;             // 0=x 1=m 2=d
    const int ll = lr % 32;
    const long lbase = ((long)(2 * bid + ls) * 3 + lc) * TT * 64;

    if (tid < 192) {
        float2 v = *(const float2*)&inputs[lbase + 2 * ll];
        *(float2*)&inb[lc * 128 + ls * 64 + 2 * ll] = v;
    }

    // ---- phase A / B lane decompositions ----
    const int jobA = w * 16 + (lane & 15);   // [0,128): g*64 + j
    const int khA  = lane >> 4;
    const int gA   = jobA >> 6;              // warp-uniform
    const int jA   = jobA & 63;
    const int qqB  = lane & 3;               // k-quarter
    const int jjB  = w * 8 + (lane >> 2);    // [0,64)

    __syncthreads();

    int p = 0;
    for (int t = 0; t < TT; t++) {
        float* bufc = inb + p * 384;

        float2 pf = make_float2(0.f, 0.f);
        if (tid < 192 && t + 1 < TT)
            pf = *(const float2*)&inputs[lbase + (long)(t + 1) * 64 + 2 * ll];

        // ===== Phase A: x_hat pre (h@W_hist) | gamma_h pre (d@W_gh) =====
        {
            const float* act = gA ? (bufc + 256) : hS;
            const float* W   = gA ? sWgh2 : sWh2;
            ull a0 = 0, a1 = 0;
#pragma unroll
            for (int i = 0; i < 8; i++) {
                int k = khA * 32 + 4 * i, q = k >> 1;
                ulonglong2 x0 = *(const ulonglong2*)&act[k];
                ulonglong2 x1 = *(const ulonglong2*)&act[64 + k];
                ull wa = *(const ull*)&W[(q * 64 + jA) * 2];
                ull wb = *(const ull*)&W[((q + 1) * 64 + jA) * 2];
                FMA2(a0, wa, x0.x); FMA2(a0, wb, x0.y);
                FMA2(a1, wa, x1.x); FMA2(a1, wb, x1.y);
            }
            float2 r0 = upk(a0), r1 = upk(a1);
            float v0 = r0.x + r0.y, v1 = r1.x + r1.y;
            v0 += __shfl_xor_sync(0xffffffffu, v0, 16);
            v1 += __shfl_xor_sync(0xffffffffu, v1, 16);
            if (lane < 16) {
                if (gA == 0) {
                    float xh0 = v0 + sbh[jA], xh1 = v1 + sbh[jA];
                    xhat[jA]      = xh0;
                    xhat[64 + jA] = xh1;
                    float x0s = bufc[jA],      m0 = bufc[128 + jA], d0 = bufc[256 + jA];
                    float x1s = bufc[64 + jA], m1 = bufc[192 + jA], d1 = bufc[320 + jA];
                    actB[jA]             = m0 * x0s + (1.f - m0) * xh0;
                    actB[192 + jA]       = m1 * x1s + (1.f - m1) * xh1;
                    actB[64 + jA]        = __expf(-fmaxf(d0 * sWgx[jA] + sbgx[jA], 0.f));
                    actB[192 + 64 + jA]  = __expf(-fmaxf(d1 * sWgx[jA] + sbgx[jA], 0.f));
                    actB[128 + jA]       = m0;
                    actB[192 + 128 + jA] = m1;
                    long n0 = 2 * bid, n1 = n0 + 1;
                    out[((n0 * 3 + 0) * (long)TT + t) * 64 + jA] = xh0;
                    out[((n1 * 3 + 0) * (long)TT + t) * 64 + jA] = xh1;
                } else {
                    float gh0 = __expf(-fmaxf(v0 + sbgh[jA], 0.f));
                    float gh1 = __expf(-fmaxf(v1 + sbgh[jA], 0.f));
                    actC[128 + jA]       = hS[jA]      * gh0;
                    actC[192 + 128 + jA] = hS[64 + jA] * gh1;
                }
            }
        }
        __syncthreads();

        // ===== Phase B: z_hat (xc@W_feat_c) + beta pre ([gx;m]@W_beta) =====
        {
            ull z0 = 0, z1 = 0, b0 = 0, b1 = 0;
#pragma unroll
            for (int i = 0; i < 4; i++) {            // z_hat: pairs qq*8..+7
                int q = qqB * 8 + 2 * i;
                ulonglong2 x0 = *(const ulonglong2*)&actB[2 * q];
                ulonglong2 x1 = *(const ulonglong2*)&actB[192 + 2 * q];
                ull wa = *(const ull*)&sWzb[(q * 64 + jjB) * 2];
                ull wb = *(const ull*)&sWzb[((q + 1) * 64 + jjB) * 2];
                FMA2(z0, wa, x0.x); FMA2(z0, wb, x0.y);
                FMA2(z1, wa, x1.x); FMA2(z1, wb, x1.y);
            }
#pragma unroll
            for (int i = 0; i < 8; i++) {            // beta: pairs 32+qq*16..+15
                int q = 32 + qqB * 16 + 2 * i;
                ulonglong2 x0 = *(const ulonglong2*)&actB[2 * q];
                ulonglong2 x1 = *(const ulonglong2*)&actB[192 + 2 * q];
                ull wa = *(const ull*)&sWzb[(q * 64 + jjB) * 2];
                ull wb = *(const ull*)&sWzb[((q + 1) * 64 + jjB) * 2];
                FMA2(b0, wa, x0.x); FMA2(b0, wb, x0.y);
                FMA2(b1, wa, x1.x); FMA2(b1, wb, x1.y);
            }
            float2 rz0 = upk(z0), rz1 = upk(z1), rb0 = upk(b0), rb1 = upk(b1);
            float zv0 = rz0.x + rz0.y, zv1 = rz1.x + rz1.y;
            float bv0 = rb0.x + rb0.y, bv1 = rb1.x + rb1.y;
#pragma unroll
            for (int off = 1; off <= 2; off <<= 1) {
                zv0 += __shfl_xor_sync(0xffffffffu, zv0, off);
                zv1 += __shfl_xor_sync(0xffffffffu, zv1, off);
                bv0 += __shfl_xor_sync(0xffffffffu, bv0, off);
                bv1 += __shfl_xor_sync(0xffffffffu, bv1, off);
            }
            if ((lane & 3) == 0) {
                float zh0 = zv0 + sbf[jjB], zh1 = zv1 + sbf[jjB];
                float be0 = sigf(bv0 + sbb[jjB]);
                float be1 = sigf(bv1 + sbb[jjB]);
                float ch0 = be0 * zh0 + (1.f - be0) * xhat[jjB];
                float ch1 = be1 * zh1 + (1.f - be1) * xhat[64 + jjB];
                float x0s = bufc[jjB],      m0 = bufc[128 + jjB];
                float x1s = bufc[64 + jjB], m1 = bufc[192 + jjB];
                actC[jjB]            = m0 * x0s + (1.f - m0) * ch0;
                actC[192 + jjB]      = m1 * x1s + (1.f - m1) * ch1;
                actC[64 + jjB]       = m0;
                actC[192 + 64 + jjB] = m1;
                long n0 = 2 * bid, n1 = n0 + 1;
                out[((n0 * 3 + 1) * (long)TT + t) * 64 + jjB] = zh0;
                out[((n1 * 3 + 1) * (long)TT + t) * 64 + jjB] = zh1;
                out[((n0 * 3 + 2) * (long)TT + t) * 64 + jjB] = ch0;
                out[((n1 * 3 + 2) * (long)TT + t) * 64 + jjB] = ch1;
            }
        }
        __syncthreads();

        // ===== Phase C: z[col] = [cc;m;hdec] @ [W_lstm;U], full k, 1 col/thr
        {
            ull acc0 = 0, acc1 = 0;
#pragma unroll
            for (int i = 0; i < 48; i++) {
                ulonglong2 x0 = *(const ulonglong2*)&actC[4 * i];
                ulonglong2 x1 = *(const ulonglong2*)&actC[192 + 4 * i];
                FMA2(acc0, wc[2*i], x0.x); FMA2(acc0, wc[2*i+1], x0.y);
                FMA2(acc1, wc[2*i], x1.x); FMA2(acc1, wc[2*i+1], x1.y);
            }
            float2 r0 = upk(acc0), r1 = upk(acc1);
            float z0 = r0.x + r0.y + blC;        // own gate value, sample 0
            float z1 = r1.x + r1.y + blC;        // sample 1
            // gather the 4 gates of column jC into gate-0 lane (3 shfl each)
            float f0 = __shfl_xor_sync(0xffffffffu, z0, 1);
            float f1 = __shfl_xor_sync(0xffffffffu, z1, 1);
            float g0 = __shfl_xor_sync(0xffffffffu, z0, 2);
            float g1 = __shfl_xor_sync(0xffffffffu, z1, 2);
            float o0 = __shfl_xor_sync(0xffffffffu, f0, 2);
            float o1 = __shfl_xor_sync(0xffffffffu, f1, 2);
            if (gC == 0) {
                float cn0 = sigf(f0) * cS[jC]      + sigf(z0) * tanhf(g0);
                float cn1 = sigf(f1) * cS[64 + jC] + sigf(z1) * tanhf(g1);
                cS[jC]      = cn0;
                cS[64 + jC] = cn1;
                hS[jC]      = sigf(o0) * tanhf(cn0);
                hS[64 + jC] = sigf(o1) * tanhf(cn1);
            }
        }
        if (tid < 192 && t + 1 < TT)
            *(float2*)&inb[(p ^ 1) * 384 + lc * 128 + ls * 64 + 2 * ll] = pf;
        p ^= 1;
        __syncthreads();
    }

    // ===== predictions: sigmoid(h_last @ W_out + b_out) =====
    if (tid < 64) {
        int s = tid >> 5, l = tid & 31;
        float v = hS[s * 64 + l] * W_out[l] + hS[s * 64 + 32 + l] * W_out[32 + l];
#pragma unroll
        for (int off = 16; off; off >>= 1)
            v += __shfl_down_sync(0xffffffffu, v, off);
        if (l == 0)
            out[NIMP + 2 * bid + s] = 1.f / (1.f + __expf(-(v + b_out[0])));
    }
}

extern "C" void kernel_launch(void* const* d_in, const int* in_sizes, int n_in,
                              void* d_out, int out_size)
{
    const float* inputs = (const float*)d_in[0];
    const float* W_hist = (const float*)d_in[1];
    const float* b_hist = (const float*)d_in[2];
    const float* W_feat = (const float*)d_in[3];
    const float* b_feat = (const float*)d_in[4];
    const float* W_gx   = (const float*)d_in[5];
    const float* b_gx   = (const float*)d_in[6];
    const float* W_gh   = (const float*)d_in[7];
    const float* b_gh   = (const float*)d_in[8];
    const float* W_beta = (const float*)d_in[9];
    const float* b_beta = (const float*)d_in[10];
    const float* W_lstm = (const float*)d_in[11];
    const float* U_lstm = (const float*)d_in[12];
    const float* b_lstm = (const float*)d_in[13];
    const float* W_out  = (const float*)d_in[14];
    const float* b_out  = (const float*)d_in[15];

    const int smem_bytes = 23040 * (int)sizeof(float);   // 92,160 B
    cudaFuncSetAttribute(rits_kernel,
                         cudaFuncAttributeMaxDynamicSharedMemorySize, smem_bytes);

    rits_kernel<<<128, 256, smem_bytes>>>(
        inputs, W_hist, b_hist, W_feat, b_feat, W_gx, b_gx, W_gh, b_gh,
        W_beta, b_beta, W_lstm, U_lstm, b_lstm, W_out, b_out,
        (float*)d_out);
}

// round 7
// speedup vs baseline: 1.8934x; 1.8782x over previous
#include <cuda_runtime.h>
#include <cuda_bf16.h>

// RITS recurrence v6: v2 phases A/B (proven conflict-free) + new phase C.
//  - 128 CTAs x 256 thr, 2 samples/CTA, T=512 on-chip.
//  - Phase C: thread = (k-half, gate-pair, column j); 96 ull register weights,
//    act loads lane-split over k-halves via bank-padded actC chunks (1 wf),
//    kc-reduce + gate exchange via shfl_xor, LSTM cell inline (no zbuf/C2).
//  - 5 barriers/step.

#define TT 512
#define NIMP (256L * 3 * 512 * 64)
typedef unsigned long long ull;

#define FMA2(acc, a, b) \
    asm("fma.rn.f32x2 %0, %1, %2, %0;" : "+l"(acc) : "l"(a), "l"(b))

__device__ __forceinline__ ull pk2(float x, float y) {
    ull r; asm("mov.b64 %0, {%1, %2};" : "=l"(r) : "f"(x), "f"(y)); return r;
}
__device__ __forceinline__ float2 upk(ull v) {
    float2 r; asm("mov.b64 {%0, %1}, %2;" : "=f"(r.x), "=f"(r.y) : "l"(v)); return r;
}
__device__ __forceinline__ float sigf(float x) { return 1.f / (1.f + __expf(-x)); }

__global__ __launch_bounds__(256, 1) void rits_kernel(
    const float* __restrict__ inputs,
    const float* __restrict__ W_hist, const float* __restrict__ b_hist,
    const float* __restrict__ W_feat, const float* __restrict__ b_feat,
    const float* __restrict__ W_gx,   const float* __restrict__ b_gx,
    const float* __restrict__ W_gh,   const float* __restrict__ b_gh,
    const float* __restrict__ W_beta, const float* __restrict__ b_beta,
    const float* __restrict__ W_lstm, const float* __restrict__ U_lstm,
    const float* __restrict__ b_lstm,
    const float* __restrict__ W_out,  const float* __restrict__ b_out,
    float* __restrict__ out)
{
    extern __shared__ __align__(16) float sm[];
    float* sWh2  = sm;             // 4096  W_hist pairs {w[2q][j],w[2q+1][j]}
    float* sWf2  = sWh2  + 4096;   // 4096  W_feat (diag zeroed) pairs
    float* sWb2  = sWf2  + 4096;   // 8192  W_beta pairs
    float* sWgh2 = sWb2  + 8192;   // 4096  W_gh pairs
    float* sWgx  = sWgh2 + 4096;   // 64    diag(W_gx)
    float* sbh   = sWgx + 64;
    float* sbf   = sbh  + 64;
    float* sbgx  = sbf  + 64;
    float* sbb   = sbgx + 64;
    float* sbgh  = sbb  + 64;
    float* hS    = sbgh + 64;      // 128  h [s*64+j]
    float* cS    = hS   + 128;     // 128
    float* xhat  = cS   + 128;     // 128  [s*64+j]
    float* xc    = xhat + 128;     // 128  [s*64+j]
    float* gx    = xc   + 128;     // 128  [s*64+j]
    float* actC  = gx   + 128;     // 400  4 chunks(s,kc) x 100:
                                   //      rows [cc(64)|m(64)|hdec(64)] split at 96
    float* pA    = actC + 400;     // 512  phase-A partials [(g*2+kh)][s][j]
    float* pz    = pA   + 512;     // 256
    float* pb    = pz   + 256;     // 512
    float* inb   = pb   + 512;     // 2*384 double-buffered [c*128 + s*64 + k]

    const int tid  = threadIdx.x;
    const int bid  = blockIdx.x;
    const int lane = tid & 31;
    const int w    = tid >> 5;

    // ---- pack smem weights (v2 layout: pairs {W[2q][j],W[2q+1][j]}) ----
    for (int i = tid; i < 2048; i += 256) {
        int q = i >> 6, j = i & 63;
        *(float2*)&sWh2[i * 2]  = make_float2(W_hist[(2*q)*64 + j], W_hist[(2*q+1)*64 + j]);
        *(float2*)&sWgh2[i * 2] = make_float2(W_gh[(2*q)*64 + j],   W_gh[(2*q+1)*64 + j]);
    }
    for (int i = tid; i < 2048; i += 256) {
        int q = i >> 6, j = i & 63;
        float a = (2*q     == j) ? 0.f : W_feat[(2*q)*64 + j];
        float b = (2*q + 1 == j) ? 0.f : W_feat[(2*q+1)*64 + j];
        *(float2*)&sWf2[i * 2] = make_float2(a, b);
    }
    for (int i = tid; i < 4096; i += 256) {
        int q = i >> 6, j = i & 63;
        *(float2*)&sWb2[i * 2] = make_float2(W_beta[(2*q)*64 + j], W_beta[(2*q+1)*64 + j]);
    }
    if (tid < 64) {
        sWgx[tid] = W_gx[tid * 64 + tid];
        sbh[tid]  = b_hist[tid];
        sbf[tid]  = b_feat[tid];
        sbgx[tid] = b_gx[tid];
        sbb[tid]  = b_beta[tid];
        sbgh[tid] = b_gh[tid];
    }
    if (tid < 128) { hS[tid] = 0.f; cS[tid] = 0.f; }

    // ---- phase C register weights: (k-half, gate-pair, j) ----
    // lane = jl*4 + gp*2 + kc ; j = w*8 + jl
    // colA = gp*64 + j (gate i or f), colB = colA + 128 (gate g or o)
    const int kcC = lane & 1;
    const int gpC = (lane >> 1) & 1;
    const int jCc = w * 8 + (lane >> 2);
    const int colA = gpC * 64 + jCc;
    const int colB = colA + 128;
    ull wA[48], wB[48];
#pragma unroll
    for (int u = 0; u < 48; u++) {
        int p = kcC * 48 + u;
        int r0 = 2 * p, r1 = r0 + 1;
        float a0 = (r0 < 128) ? W_lstm[r0 * 256 + colA] : U_lstm[(r0 - 128) * 256 + colA];
        float a1 = (r1 < 128) ? W_lstm[r1 * 256 + colA] : U_lstm[(r1 - 128) * 256 + colA];
        float b0 = (r0 < 128) ? W_lstm[r0 * 256 + colB] : U_lstm[(r0 - 128) * 256 + colB];
        float b1 = (r1 < 128) ? W_lstm[r1 * 256 + colB] : U_lstm[(r1 - 128) * 256 + colB];
        wA[u] = pk2(a0, a1);
        wB[u] = pk2(b0, b1);
    }
    const float blA = b_lstm[colA];
    const float blB = b_lstm[colB];

    // ---- input loader mapping (threads 0..191) ----
    const int ls = tid / 96;
    const int lr = tid % 96;
    const int lc = lr / 32;             // 0=x 1=m 2=d
    const int ll = lr % 32;
    const long lbase = ((long)(2 * bid + ls) * 3 + lc) * TT * 64;

    if (tid < 192) {
        float2 v = *(const float2*)&inputs[lbase + 2 * ll];
        *(float2*)&inb[lc * 128 + ls * 64 + 2 * ll] = v;
    }
    __syncthreads();

    // ---- phase A / B decompositions (v2) ----
    const int g  = tid >> 7;            // phase A: 0 -> x_hat, 1 -> gamma_h
    const int kh = (tid >> 6) & 1;      // phase A k-half
    const int jA = tid & 63;
    const int u  = tid >> 6;            // phase B quarter
    const int jB = tid & 63;

    int p = 0;
    for (int t = 0; t < TT; t++) {
        float* bufc = inb + p * 384;

        float2 pf = make_float2(0.f, 0.f);
        if (tid < 192 && t + 1 < TT)
            pf = *(const float2*)&inputs[lbase + (long)(t + 1) * 64 + 2 * ll];

        // ===== Phase A: x_hat pre (h@W_hist) / gamma_h pre (d@W_gh) =====
        {
            const float* act = g ? (bufc + 256) : hS;
            const float* W   = g ? sWgh2 : sWh2;
            ull acc0 = 0, acc1 = 0;
#pragma unroll
            for (int i = 0; i < 8; i++) {
                int k = kh * 32 + 4 * i, q = k >> 1;
                ulonglong2 a0 = *(const ulonglong2*)&act[k];
                ulonglong2 a1 = *(const ulonglong2*)&act[64 + k];
                ull wa = *(const ull*)&W[(q * 64 + jA) * 2];
                ull wb = *(const ull*)&W[((q + 1) * 64 + jA) * 2];
                FMA2(acc0, wa, a0.x); FMA2(acc0, wb, a0.y);
                FMA2(acc1, wa, a1.x); FMA2(acc1, wb, a1.y);
            }
            float2 r0 = upk(acc0), r1 = upk(acc1);
            pA[(g * 2 + kh) * 128 + jA]      = r0.x + r0.y;
            pA[(g * 2 + kh) * 128 + 64 + jA] = r1.x + r1.y;
        }
        __syncthreads();

        // ===== Phase A2: x_hat, x_c, gamma_x | gamma_h, h_dec =====
        {
            int r = tid & 127, s = r >> 6, j = r & 63;
            if (g == 0) {
                float v = pA[s * 64 + j] + pA[128 + s * 64 + j] + sbh[j];
                xhat[r] = v;
                float x = bufc[r], m = bufc[128 + r], d = bufc[256 + r];
                xc[r] = m * x + (1.f - m) * v;
                gx[r] = __expf(-fmaxf(d * sWgx[j] + sbgx[j], 0.f));
                long n = 2 * bid + s;
                out[((n * 3 + 0) * (long)TT + t) * 64 + j] = v;
            } else {
                float v = pA[256 + s * 64 + j] + pA[384 + s * 64 + j];
                float gh = __expf(-fmaxf(v + sbgh[j], 0.f));
                // hdec: fused row 128+j -> chunk (s,kc=1), local 32+j
                actC[s * 200 + 100 + 32 + j] = hS[r] * gh;
            }
        }
        __syncthreads();

        // ===== Phase B: z_hat (xc@W_feat_c) + beta pre ([gx;m]@W_beta) =====
        {
            ull z0 = 0, z1 = 0, b0 = 0, b1 = 0;
            if (u < 2) {
#pragma unroll
                for (int i = 0; i < 8; i++) {            // z_hat, 32 k
                    int k = u * 32 + 4 * i, q = k >> 1;
                    ulonglong2 a0 = *(const ulonglong2*)&xc[k];
                    ulonglong2 a1 = *(const ulonglong2*)&xc[64 + k];
                    ull wa = *(const ull*)&sWf2[(q * 64 + jB) * 2];
                    ull wb = *(const ull*)&sWf2[((q + 1) * 64 + jB) * 2];
                    FMA2(z0, wa, a0.x); FMA2(z0, wb, a0.y);
                    FMA2(z1, wa, a1.x); FMA2(z1, wb, a1.y);
                }
#pragma unroll
                for (int i = 0; i < 4; i++) {            // beta, 16 k (gamma_x)
                    int k = u * 16 + 4 * i, q = k >> 1;
                    ulonglong2 a0 = *(const ulonglong2*)&gx[k];
                    ulonglong2 a1 = *(const ulonglong2*)&gx[64 + k];
                    ull wa = *(const ull*)&sWb2[(q * 64 + jB) * 2];
                    ull wb = *(const ull*)&sWb2[((q + 1) * 64 + jB) * 2];
                    FMA2(b0, wa, a0.x); FMA2(b0, wb, a0.y);
                    FMA2(b1, wa, a1.x); FMA2(b1, wb, a1.y);
                }
                float2 r0 = upk(z0), r1 = upk(z1);
                pz[u * 128 + jB]      = r0.x + r0.y;
                pz[u * 128 + 64 + jB] = r1.x + r1.y;
            } else if (u == 2) {
#pragma unroll
                for (int i = 0; i < 8; i++) {            // beta, k 32..63 (gamma_x)
                    int k = 32 + 4 * i, q = k >> 1;
                    ulonglong2 a0 = *(const ulonglong2*)&gx[k];
                    ulonglong2 a1 = *(const ulonglong2*)&gx[64 + k];
                    ull wa = *(const ull*)&sWb2[(q * 64 + jB) * 2];
                    ull wb = *(const ull*)&sWb2[((q + 1) * 64 + jB) * 2];
                    FMA2(b0, wa, a0.x); FMA2(b0, wb, a0.y);
                    FMA2(b1, wa, a1.x); FMA2(b1, wb, a1.y);
                }
#pragma unroll
                for (int i = 0; i < 4; i++) {            // beta, k 64..79 (m)
                    int k = 64 + 4 * i, q = k >> 1;
                    ulonglong2 a0 = *(const ulonglong2*)&bufc[128 + (k - 64)];
                    ulonglong2 a1 = *(const ulonglong2*)&bufc[128 + 64 + (k - 64)];
                    ull wa = *(const ull*)&sWb2[(q * 64 + jB) * 2];
                    ull wb = *(const ull*)&sWb2[((q + 1) * 64 + jB) * 2];
                    FMA2(b0, wa, a0.x); FMA2(b0, wb, a0.y);
                    FMA2(b1, wa, a1.x); FMA2(b1, wb, a1.y);
                }
            } else {
#pragma unroll
                for (int i = 0; i < 12; i++) {           // beta, k 80..127 (m)
                    int k = 80 + 4 * i, q = k >> 1;
                    ulonglong2 a0 = *(const ulonglong2*)&bufc[128 + (k - 64)];
                    ulonglong2 a1 = *(const ulonglong2*)&bufc[128 + 64 + (k - 64)];
                    ull wa = *(const ull*)&sWb2[(q * 64 + jB) * 2];
                    ull wb = *(const ull*)&sWb2[((q + 1) * 64 + jB) * 2];
                    FMA2(b0, wa, a0.x); FMA2(b0, wb, a0.y);
                    FMA2(b1, wa, a1.x); FMA2(b1, wb, a1.y);
                }
            }
            float2 r0 = upk(b0), r1 = upk(b1);
            pb[u * 128 + jB]      = r0.x + r0.y;
            pb[u * 128 + 64 + jB] = r1.x + r1.y;
        }
        __syncthreads();

        // ===== Phase B2: beta, c_hat, c_c (+ m into actC) =====
        if (tid < 128) {
            int s = tid >> 6, j = tid & 63, r = tid;
            float zh   = pz[r] + pz[128 + r] + sbf[j];
            float bpre = pb[r] + pb[128 + r] + pb[256 + r] + pb[384 + r] + sbb[j];
            float beta = sigf(bpre);
            float chat = beta * zh + (1.f - beta) * xhat[r];
            float x = bufc[r], m = bufc[128 + r];
            float cc = m * x + (1.f - m) * chat;
            // cc: fused row j -> chunk (s,0), local j
            actC[s * 200 + j] = cc;
            // m: fused row 64+j -> chunk (s,0) local 64+j if j<32 else (s,1) local j-32
            if (j < 32) actC[s * 200 + 64 + j] = m;
            else        actC[s * 200 + 100 + (j - 32)] = m;
            long n = 2 * bid + s;
            out[((n * 3 + 1) * (long)TT + t) * 64 + j] = zh;
            out[((n * 3 + 2) * (long)TT + t) * 64 + j] = chat;
        }
        __syncthreads();

        // ===== Phase C: z = [cc;m;hdec] @ [W_lstm;U], regs, kc lane-split ====
        {
            ull aA0 = 0, aA1 = 0, aB0 = 0, aB1 = 0;
            const float* c0 = actC + kcC * 100;          // sample 0, own k-half
            const float* c1 = actC + 200 + kcC * 100;    // sample 1
#pragma unroll
            for (int q = 0; q < 24; q++) {
                ulonglong2 L0 = *(const ulonglong2*)&c0[4 * q];
                ulonglong2 L1 = *(const ulonglong2*)&c1[4 * q];
                FMA2(aA0, wA[2*q], L0.x); FMA2(aA0, wA[2*q+1], L0.y);
                FMA2(aB0, wB[2*q], L0.x); FMA2(aB0, wB[2*q+1], L0.y);
                FMA2(aA1, wA[2*q], L1.x); FMA2(aA1, wA[2*q+1], L1.y);
                FMA2(aB1, wB[2*q], L1.x); FMA2(aB1, wB[2*q+1], L1.y);
            }
            float2 r;
            r = upk(aA0); float vA0 = r.x + r.y;
            r = upk(aA1); float vA1 = r.x + r.y;
            r = upk(aB0); float vB0 = r.x + r.y;
            r = upk(aB1); float vB1 = r.x + r.y;
            // reduce k-halves (partner lane^1)
            vA0 += __shfl_xor_sync(0xffffffffu, vA0, 1);
            vA1 += __shfl_xor_sync(0xffffffffu, vA1, 1);
            vB0 += __shfl_xor_sync(0xffffffffu, vB0, 1);
            vB1 += __shfl_xor_sync(0xffffffffu, vB1, 1);
            vA0 += blA; vA1 += blA; vB0 += blB; vB1 += blB;
            // gate-pair exchange (lane^2): (i,g) <-> (f,o)
            float pA0 = __shfl_xor_sync(0xffffffffu, vA0, 2);
            float pA1 = __shfl_xor_sync(0xffffffffu, vA1, 2);
            float pB0 = __shfl_xor_sync(0xffffffffu, vB0, 2);
            float pB1 = __shfl_xor_sync(0xffffffffu, vB1, 2);
            if ((lane & 3) == 0) {
                // gp=0 lane: own (i, g); partner (f, o)
                float cn0 = sigf(pA0) * cS[jCc]      + sigf(vA0) * tanhf(vB0);
                float cn1 = sigf(pA1) * cS[64 + jCc] + sigf(vA1) * tanhf(vB1);
                cS[jCc]      = cn0;
                cS[64 + jCc] = cn1;
                hS[jCc]      = sigf(pB0) * tanhf(cn0);
                hS[64 + jCc] = sigf(pB1) * tanhf(cn1);
            }
        }
        if (tid < 192 && t + 1 < TT)
            *(float2*)&inb[(p ^ 1) * 384 + lc * 128 + ls * 64 + 2 * ll] = pf;
        p ^= 1;
        __syncthreads();
    }

    // ===== predictions: sigmoid(h_last @ W_out + b_out) =====
    if (tid < 64) {
        int s = tid >> 5, l = tid & 31;
        float v = hS[s * 64 + l] * W_out[l] + hS[s * 64 + 32 + l] * W_out[32 + l];
#pragma unroll
        for (int off = 16; off; off >>= 1)
            v += __shfl_down_sync(0xffffffffu, v, off);
        if (l == 0)
            out[NIMP + 2 * bid + s] = 1.f / (1.f + __expf(-(v + b_out[0])));
    }
}

extern "C" void kernel_launch(void* const* d_in, const int* in_sizes, int n_in,
                              void* d_out, int out_size)
{
    const float* inputs = (const float*)d_in[0];
    const float* W_hist = (const float*)d_in[1];
    const float* b_hist = (const float*)d_in[2];
    const float* W_feat = (const float*)d_in[3];
    const float* b_feat = (const float*)d_in[4];
    const float* W_gx   = (const float*)d_in[5];
    const float* b_gx   = (const float*)d_in[6];
    const float* W_gh   = (const float*)d_in[7];
    const float* b_gh   = (const float*)d_in[8];
    const float* W_beta = (const float*)d_in[9];
    const float* b_beta = (const float*)d_in[10];
    const float* W_lstm = (const float*)d_in[11];
    const float* U_lstm = (const float*)d_in[12];
    const float* b_lstm = (const float*)d_in[13];
    const float* W_out  = (const float*)d_in[14];
    const float* b_out  = (const float*)d_in[15];

    const int smem_bytes = 24000 * (int)sizeof(float);   // 96,000 B
    cudaFuncSetAttribute(rits_kernel,
                         cudaFuncAttributeMaxDynamicSharedMemorySize, smem_bytes);

    rits_kernel<<<128, 256, smem_bytes>>>(
        inputs, W_hist, b_hist, W_feat, b_feat, W_gx, b_gx, W_gh, b_gh,
        W_beta, b_beta, W_lstm, U_lstm, b_lstm, W_out, b_out,
        (float*)d_out);
}